// round 16
// baseline (speedup 1.0000x reference)
#include <cuda_runtime.h>
#include <cuda_bf16.h>
#include <cstdint>

#define TT    100
#define BB    200
#define NGG   4096
#define NPP   512
#define TBROWS (TT * BB)   // 20000
#define MPAD  256
#define KC    128
#define NC    (NGG / KC)   // 32
#define KCD   64
#define NCD   (NGG / KCD)  // 64 (decoder)

typedef unsigned long long u64;
#define SLOT ((size_t)MPAD * NGG)

// ---------------- static device scratch (allocation-free) ----------------
__device__ __nv_bfloat16 ghi_buf[(size_t)(TT + 1) * MPAD * NGG];  // 212 MB, pad rows stay 0
__device__ __nv_bfloat16 glo_buf[(size_t)(TT + 1) * MPAD * NGG];  // 212 MB
__device__ __nv_bfloat16 Whi_d[(size_t)NGG * NGG];                // 33.5 MB
__device__ __nv_bfloat16 Wlo_d[(size_t)NGG * NGG];                // 33.5 MB
__device__ __nv_bfloat16 decWhi[(size_t)1024 * NGG];              // 8.4 MB
__device__ __nv_bfloat16 decWlo[(size_t)1024 * NGG];

// ---------------- helpers ----------------
static __device__ __forceinline__ uint32_t smem_u32(const void* p) {
    uint32_t a;
    asm("{ .reg .u64 t; cvta.to.shared.u64 t, %1; cvt.u32.u64 %0, t; }" : "=r"(a) : "l"(p));
    return a;
}
static __device__ __forceinline__ void cpa16(uint32_t d, const void* g) {
    asm volatile("cp.async.cg.shared.global [%0], [%1], 16;" :: "r"(d), "l"(g));
}
static __device__ __forceinline__ void cpa16z(uint32_t d, const void* g, uint32_t n) {
    asm volatile("cp.async.cg.shared.global [%0], [%1], 16, %2;" :: "r"(d), "l"(g), "r"(n));
}
#define CP_COMMIT() asm volatile("cp.async.commit_group;" ::: "memory")
#define CP_WAIT1()  asm volatile("cp.async.wait_group 1;" ::: "memory")
#define SWZ(x) ((x) ^ (((x) >> 3) & 0x70))

static __device__ __forceinline__ void ldsm4(uint32_t* r, uint32_t a) {
    asm volatile("ldmatrix.sync.aligned.m8n8.x4.shared.b16 {%0,%1,%2,%3}, [%4];"
                 : "=r"(r[0]), "=r"(r[1]), "=r"(r[2]), "=r"(r[3]) : "r"(a));
}
static __device__ __forceinline__ void mma_bf16(float* c, const uint32_t* a, const uint32_t* b) {
    asm volatile("mma.sync.aligned.m16n8k16.row.col.f32.bf16.bf16.f32 "
                 "{%0,%1,%2,%3},{%4,%5,%6,%7},{%8,%9},{%0,%1,%2,%3};"
                 : "+f"(c[0]), "+f"(c[1]), "+f"(c[2]), "+f"(c[3])
                 : "r"(a[0]), "r"(a[1]), "r"(a[2]), "r"(a[3]), "r"(b[0]), "r"(b[1]));
}

// ---- 32M x 32N warp tile over one 64-wide k sub-chunk, bf16x3, term-major ----
static __device__ __forceinline__ void mma_chunk32(uint32_t sAhi, uint32_t sAlo,
                                                   uint32_t sBhi, uint32_t sBlo,
                                                   int aRowBase, int bRowBase, int lane,
                                                   float (*acc)[4][4]) {   // acc[2][4][4]
#pragma unroll
    for (int j = 0; j < 4; j++) {
        uint32_t aHi[2][4], aLo[2][4], bHi[4][2], bLo[4][2];
        int kbA = j * 32 + (lane & 16);
#pragma unroll
        for (int mg = 0; mg < 2; mg++) {
            int row = aRowBase + 16 * mg + (lane & 15);
            uint32_t off = SWZ((uint32_t)(row * 128 + kbA));
            ldsm4(aHi[mg], sAhi + off);
            ldsm4(aLo[mg], sAlo + off);
        }
        int kbB = j * 32 + ((lane & 8) << 1);
#pragma unroll
        for (int p = 0; p < 2; p++) {
            int nrow = bRowBase + 16 * p + ((lane & 16) >> 1) + (lane & 7);
            uint32_t off = SWZ((uint32_t)(nrow * 128 + kbB));
            uint32_t r4[4], s4[4];
            ldsm4(r4, sBhi + off);
            ldsm4(s4, sBlo + off);
            bHi[2 * p][0] = r4[0]; bHi[2 * p][1] = r4[1];
            bHi[2 * p + 1][0] = r4[2]; bHi[2 * p + 1][1] = r4[3];
            bLo[2 * p][0] = s4[0]; bLo[2 * p][1] = s4[1];
            bLo[2 * p + 1][0] = s4[2]; bLo[2 * p + 1][1] = s4[3];
        }
#pragma unroll
        for (int mg = 0; mg < 2; mg++)
#pragma unroll
            for (int ng = 0; ng < 4; ng++) mma_bf16(acc[mg][ng], aHi[mg], bHi[ng]);
#pragma unroll
        for (int mg = 0; mg < 2; mg++)
#pragma unroll
            for (int ng = 0; ng < 4; ng++) mma_bf16(acc[mg][ng], aHi[mg], bLo[ng]);
#pragma unroll
        for (int mg = 0; mg < 2; mg++)
#pragma unroll
            for (int ng = 0; ng < 4; ng++) mma_bf16(acc[mg][ng], aLo[mg], bHi[ng]);
    }
}

// ---- 64M x 32N warp tile (decoder) ----
static __device__ __forceinline__ void mma_chunk(uint32_t sAhi, uint32_t sAlo,
                                                 uint32_t sBhi, uint32_t sBlo,
                                                 int aRowBase, int bRowBase, int lane,
                                                 float (*acc)[4][4]) {   // acc[4][4][4]
#pragma unroll
    for (int j = 0; j < 4; j++) {
        uint32_t aHi[4][4], aLo[4][4], bHi[4][2], bLo[4][2];
        int kbA = j * 32 + (lane & 16);
#pragma unroll
        for (int mg = 0; mg < 4; mg++) {
            int row = aRowBase + 16 * mg + (lane & 15);
            uint32_t off = SWZ((uint32_t)(row * 128 + kbA));
            ldsm4(aHi[mg], sAhi + off);
            ldsm4(aLo[mg], sAlo + off);
        }
        int kbB = j * 32 + ((lane & 8) << 1);
#pragma unroll
        for (int p = 0; p < 2; p++) {
            int nrow = bRowBase + 16 * p + ((lane & 16) >> 1) + (lane & 7);
            uint32_t off = SWZ((uint32_t)(nrow * 128 + kbB));
            uint32_t r4[4], s4[4];
            ldsm4(r4, sBhi + off);
            ldsm4(s4, sBlo + off);
            bHi[2 * p][0] = r4[0]; bHi[2 * p][1] = r4[1];
            bHi[2 * p + 1][0] = r4[2]; bHi[2 * p + 1][1] = r4[3];
            bLo[2 * p][0] = s4[0]; bLo[2 * p][1] = s4[1];
            bLo[2 * p + 1][0] = s4[2]; bLo[2 * p + 1][1] = s4[3];
        }
#pragma unroll
        for (int mg = 0; mg < 4; mg++)
#pragma unroll
            for (int ng = 0; ng < 4; ng++) {
                mma_bf16(acc[mg][ng], aHi[mg], bHi[ng]);
                mma_bf16(acc[mg][ng], aHi[mg], bLo[ng]);
                mma_bf16(acc[mg][ng], aLo[mg], bHi[ng]);
            }
    }
}

// ================= step: slot[t+1] = relu(vel_enc + slot[t] @ Wh^T) =========
// Block 128M x 64N, 256 threads (8 warps: 4m x 2n, warp tile 32x32).
// grid (64 n, 2 m) = 128 CTAs, 1/SM. KC=128 as two 64-wide SW128 sub-tiles,
// 2-stage ring (192KB smem). EXACT R11 configuration (best measured: 72us).
#define AHI0 0
#define ALO0 32768
#define BHI0 65536
#define BLO0 81920
#define STAGE_S 98304
__global__ void __launch_bounds__(256) step_mma(int t,
                                                const float* __restrict__ vel_t,
                                                const float* __restrict__ Wv) {
    extern __shared__ __align__(1024) char smem[];
    uint32_t sb = smem_u32(smem);
    const int tid = threadIdx.x, lane = tid & 31, w = tid >> 5;
    const int mw = w >> 1, nw = w & 1;                 // 4m x 2n
    const int nBase = blockIdx.x * 64, mBase = blockIdx.y * 128;
    const __nv_bfloat16* pAhi = ghi_buf + (size_t)t * SLOT;
    const __nv_bfloat16* pAlo = glo_buf + (size_t)t * SLOT;

    // A: 128 rows x 16 (16B units); 8 sweeps of 256 threads each for hi (and lo)
    size_t aSrc[8]; uint32_t aDst[8];
#pragma unroll
    for (int i = 0; i < 8; i++) {
        int u = i * 256 + tid, row = u >> 4, k16 = u & 15;
        int sub = k16 >> 3, k8 = k16 & 7;
        aSrc[i] = (size_t)(mBase + row) * NGG + k16 * 8;
        aDst[i] = sub * 16384 + SWZ((uint32_t)(row * 128 + k8 * 16));
    }
    // B: 64 rows x 16; 4 sweeps
    size_t bSrc[4]; uint32_t bDst[4];
#pragma unroll
    for (int i = 0; i < 4; i++) {
        int u = i * 256 + tid, row = u >> 4, k16 = u & 15;
        int sub = k16 >> 3, k8 = k16 & 7;
        bSrc[i] = (size_t)(nBase + row) * NGG + k16 * 8;
        bDst[i] = sub * 8192 + SWZ((uint32_t)(row * 128 + k8 * 16));
    }

    auto loadc = [&](int c, int s) {
        uint32_t base = sb + s * STAGE_S;
        int ko = c * KC;
#pragma unroll
        for (int i = 0; i < 8; i++) {
            cpa16(base + AHI0 + aDst[i], pAhi + aSrc[i] + ko);
            cpa16(base + ALO0 + aDst[i], pAlo + aSrc[i] + ko);
        }
#pragma unroll
        for (int i = 0; i < 4; i++) {
            cpa16(base + BHI0 + bDst[i], Whi_d + bSrc[i] + ko);
            cpa16(base + BLO0 + bDst[i], Wlo_d + bSrc[i] + ko);
        }
        CP_COMMIT();
    };

    float acc[2][4][4];
#pragma unroll
    for (int a = 0; a < 2; a++)
#pragma unroll
        for (int b = 0; b < 4; b++)
#pragma unroll
            for (int e = 0; e < 4; e++) acc[a][b][e] = 0.f;

    loadc(0, 0); loadc(1, 1);
    for (int c = 0; c < NC; c++) {
        CP_WAIT1();
        __syncthreads();
        uint32_t base = sb + (c & 1) * STAGE_S;
        mma_chunk32(base + AHI0, base + ALO0, base + BHI0, base + BLO0,
                    32 * mw, 32 * nw, lane, acc);
        mma_chunk32(base + AHI0 + 16384, base + ALO0 + 16384,
                    base + BHI0 + 8192, base + BLO0 + 8192,
                    32 * mw, 32 * nw, lane, acc);
        __syncthreads();
        if (c + 2 < NC) loadc(c + 2, c & 1); else CP_COMMIT();
    }

    __nv_bfloat16* oHi = ghi_buf + (size_t)(t + 1) * SLOT;
    __nv_bfloat16* oLo = glo_buf + (size_t)(t + 1) * SLOT;
#pragma unroll
    for (int mg = 0; mg < 2; mg++) {
        int r0 = 32 * mw + 16 * mg + (lane >> 2);
        int m0 = mBase + r0, m1 = m0 + 8;
        float v00 = 0.f, v01 = 0.f, v10 = 0.f, v11 = 0.f;
        if (m0 < BB) { v00 = vel_t[m0 * 2]; v01 = vel_t[m0 * 2 + 1]; }
        if (m1 < BB) { v10 = vel_t[m1 * 2]; v11 = vel_t[m1 * 2 + 1]; }
#pragma unroll
        for (int ng = 0; ng < 4; ng++) {
            int c0 = nBase + 32 * nw + 8 * ng + (lane & 3) * 2;
            float4 wv = *(const float4*)&Wv[c0 * 2];
            float* d = acc[mg][ng];
            if (m0 < BB) {
                float x0 = fmaxf(d[0] + v00 * wv.x + v01 * wv.y, 0.f);
                float x1 = fmaxf(d[1] + v00 * wv.z + v01 * wv.w, 0.f);
                __nv_bfloat16 h0 = __float2bfloat16(x0), h1 = __float2bfloat16(x1);
                __nv_bfloat162 hh; hh.x = h0; hh.y = h1;
                __nv_bfloat162 ll;
                ll.x = __float2bfloat16(x0 - __bfloat162float(h0));
                ll.y = __float2bfloat16(x1 - __bfloat162float(h1));
                *(__nv_bfloat162*)&oHi[(size_t)m0 * NGG + c0] = hh;
                *(__nv_bfloat162*)&oLo[(size_t)m0 * NGG + c0] = ll;
            }
            if (m1 < BB) {
                float x0 = fmaxf(d[2] + v10 * wv.x + v11 * wv.y, 0.f);
                float x1 = fmaxf(d[3] + v10 * wv.z + v11 * wv.w, 0.f);
                __nv_bfloat16 h0 = __float2bfloat16(x0), h1 = __float2bfloat16(x1);
                __nv_bfloat162 hh; hh.x = h0; hh.y = h1;
                __nv_bfloat162 ll;
                ll.x = __float2bfloat16(x0 - __bfloat162float(h0));
                ll.y = __float2bfloat16(x1 - __bfloat162float(h1));
                *(__nv_bfloat162*)&oHi[(size_t)m1 * NGG + c0] = hh;
                *(__nv_bfloat162*)&oLo[(size_t)m1 * NGG + c0] = ll;
            }
        }
    }
}

// ================= decoder: place | sigmoid(image) via bf16x3 mma ===========
// grid (8 n, 157 m), 256 threads (8 warps: 2m x 4n), 3-stage pipeline (R11).
#define STAGE_D 65536   // Ahi 16K | Alo 16K | Bhi 16K | Blo 16K
__global__ void __launch_bounds__(256) dec_mma(float* __restrict__ out) {
    extern __shared__ __align__(1024) char smem[];
    uint32_t sb = smem_u32(smem);
    const int tid = threadIdx.x, lane = tid & 31, w = tid >> 5;
    const int mh = w >> 2, wn = w & 3;
    const int nBase = blockIdx.x * 128, mBase = blockIdx.y * 128;

    size_t aSrc[4]; uint32_t aDst[4], aVal[4];
#pragma unroll
    for (int i = 0; i < 4; i++) {
        int u = i * 256 + tid, row = u >> 3, k8 = u & 7;
        int arow = mBase + row;
        bool ok = arow < TBROWS;
        int tt = ok ? (arow / 200) : 0;
        int b = ok ? (arow - tt * 200) : 0;
        aSrc[i] = ((size_t)(tt + 1) * MPAD + b) * NGG + k8 * 8;
        aDst[i] = SWZ((uint32_t)(row * 128 + k8 * 16));
        aVal[i] = ok ? 16u : 0u;
    }
    size_t bSrc[4]; uint32_t bDst[4];
#pragma unroll
    for (int i = 0; i < 4; i++) {
        int u = i * 256 + tid, row = u >> 3, k8 = u & 7;
        bSrc[i] = (size_t)(nBase + row) * NGG + k8 * 8;
        bDst[i] = SWZ((uint32_t)(row * 128 + k8 * 16));
    }

    auto loadc = [&](int c, int s) {
        uint32_t base = sb + s * STAGE_D;
        int ko = c * KCD;
#pragma unroll
        for (int i = 0; i < 4; i++) {
            cpa16z(base + aDst[i], ghi_buf + aSrc[i] + ko, aVal[i]);
            cpa16z(base + 16384 + aDst[i], glo_buf + aSrc[i] + ko, aVal[i]);
        }
#pragma unroll
        for (int i = 0; i < 4; i++) {
            cpa16(base + 32768 + bDst[i], decWhi + bSrc[i] + ko);
            cpa16(base + 49152 + bDst[i], decWlo + bSrc[i] + ko);
        }
        CP_COMMIT();
    };

    float acc[4][4][4];
#pragma unroll
    for (int a = 0; a < 4; a++)
#pragma unroll
        for (int b = 0; b < 4; b++)
#pragma unroll
            for (int e = 0; e < 4; e++) acc[a][b][e] = 0.f;

    loadc(0, 0); loadc(1, 1);
    for (int c = 0; c < NCD; c++) {
        CP_WAIT1();
        __syncthreads();
        if (c + 2 < NCD) loadc(c + 2, (c + 2) % 3); else CP_COMMIT();
        uint32_t base = sb + (c % 3) * STAGE_D;
        mma_chunk(base, base + 16384, base + 32768, base + 49152,
                  64 * mh, 32 * wn, lane, acc);
    }

    const size_t IMG_OFF = (size_t)TBROWS * NPP;
#pragma unroll
    for (int mg = 0; mg < 4; mg++) {
        int r0 = 64 * mh + 16 * mg + (lane >> 2);
        int m0 = mBase + r0, m1 = m0 + 8;
#pragma unroll
        for (int ng = 0; ng < 4; ng++) {
            int c0 = nBase + 32 * wn + 8 * ng + (lane & 3) * 2;
            float* d = acc[mg][ng];
            if (c0 < NPP) {
                if (m0 < TBROWS) *(float2*)&out[(size_t)m0 * NPP + c0] = make_float2(d[0], d[1]);
                if (m1 < TBROWS) *(float2*)&out[(size_t)m1 * NPP + c0] = make_float2(d[2], d[3]);
            } else {
                int ci = c0 - NPP;
                if (m0 < TBROWS) {
                    float2 s = make_float2(1.f / (1.f + __expf(-d[0])), 1.f / (1.f + __expf(-d[1])));
                    *(float2*)&out[IMG_OFF + (size_t)m0 * NPP + ci] = s;
                }
                if (m1 < TBROWS) {
                    float2 s = make_float2(1.f / (1.f + __expf(-d[2])), 1.f / (1.f + __expf(-d[3])));
                    *(float2*)&out[IMG_OFF + (size_t)m1 * NPP + ci] = s;
                }
            }
        }
    }
}

// ================= fused weight conversion (W_h2h + decoder W) =============
__global__ void __launch_bounds__(256) wconv_all(const float* __restrict__ W,
                                                 const float* __restrict__ Wpc,
                                                 const float* __restrict__ Wimg) {
    if (blockIdx.x < 16384) {
        size_t i = ((size_t)blockIdx.x * 256 + threadIdx.x) * 4;
        float4 w = *(const float4*)&W[i];
        __nv_bfloat16 h0 = __float2bfloat16(w.x), h1 = __float2bfloat16(w.y);
        __nv_bfloat16 h2 = __float2bfloat16(w.z), h3 = __float2bfloat16(w.w);
        Whi_d[i] = h0; Whi_d[i + 1] = h1; Whi_d[i + 2] = h2; Whi_d[i + 3] = h3;
        Wlo_d[i]     = __float2bfloat16(w.x - __bfloat162float(h0));
        Wlo_d[i + 1] = __float2bfloat16(w.y - __bfloat162float(h1));
        Wlo_d[i + 2] = __float2bfloat16(w.z - __bfloat162float(h2));
        Wlo_d[i + 3] = __float2bfloat16(w.w - __bfloat162float(h3));
    } else {
        size_t i = (((size_t)(blockIdx.x - 16384)) * 256 + threadIdx.x) * 4;
        int n = (int)(i >> 12);
        int kk = (int)(i & 4095);
        const float* src = (n < NPP) ? (Wpc + (size_t)n * NGG + kk)
                                     : (Wimg + (size_t)(n - NPP) * NGG + kk);
        float4 w = *(const float4*)src;
        __nv_bfloat16 h0 = __float2bfloat16(w.x), h1 = __float2bfloat16(w.y);
        __nv_bfloat16 h2 = __float2bfloat16(w.z), h3 = __float2bfloat16(w.w);
        decWhi[i] = h0; decWhi[i + 1] = h1; decWhi[i + 2] = h2; decWhi[i + 3] = h3;
        decWlo[i]     = __float2bfloat16(w.x - __bfloat162float(h0));
        decWlo[i + 1] = __float2bfloat16(w.y - __bfloat162float(h1));
        decWlo[i + 2] = __float2bfloat16(w.z - __bfloat162float(h2));
        decWlo[i + 3] = __float2bfloat16(w.w - __bfloat162float(h3));
    }
}

// ================= h0 (SIMT fp32, K=1024 concat) -> slot 0 hi/lo ============
static __device__ __forceinline__ u64 pack_dup(float x) {
    u64 r; asm("mov.b64 %0, {%1, %1};" : "=l"(r) : "f"(x)); return r;
}
static __device__ __forceinline__ void fma2(u64 &d, u64 a, u64 b) {
    asm("fma.rn.f32x2 %0, %1, %2, %0;" : "+l"(d) : "l"(a), "l"(b));
}
static __device__ __forceinline__ float2 unpack2(u64 v) {
    float2 f; asm("mov.b64 {%0, %1}, %2;" : "=f"(f.x), "=f"(f.y) : "l"(v)); return f;
}
static __device__ __forceinline__ void mm128(const float (*As)[128], const float (*Bs)[128],
                                             u64 acc[8][4], int ty, int tx) {
#pragma unroll
    for (int k = 0; k < 16; k++) {
        float4 av0 = *(const float4*)&As[k][ty * 8];
        float4 av1 = *(const float4*)&As[k][ty * 8 + 4];
        const u64* bp = (const u64*)&Bs[k][tx * 8];
        u64 b0 = bp[0], b1 = bp[1], b2 = bp[2], b3 = bp[3];
        u64 ad[8];
        ad[0] = pack_dup(av0.x); ad[1] = pack_dup(av0.y);
        ad[2] = pack_dup(av0.z); ad[3] = pack_dup(av0.w);
        ad[4] = pack_dup(av1.x); ad[5] = pack_dup(av1.y);
        ad[6] = pack_dup(av1.z); ad[7] = pack_dup(av1.w);
#pragma unroll
        for (int i = 0; i < 8; i++) {
            fma2(acc[i][0], ad[i], b0); fma2(acc[i][1], ad[i], b1);
            fma2(acc[i][2], ad[i], b2); fma2(acc[i][3], ad[i], b3);
        }
    }
}
static __device__ __forceinline__ void stage_store(float (*dst)[128], int lk, int lr,
                                                   float4 v0, float4 v1) {
    dst[lk + 0][lr] = v0.x; dst[lk + 1][lr] = v0.y; dst[lk + 2][lr] = v0.z; dst[lk + 3][lr] = v0.w;
    dst[lk + 4][lr] = v1.x; dst[lk + 5][lr] = v1.y; dst[lk + 6][lr] = v1.z; dst[lk + 7][lr] = v1.w;
}

__global__ void __launch_bounds__(256) h0_kernel(const float* __restrict__ init_actv,
                                                 const float* __restrict__ image0,
                                                 const float* __restrict__ Wpc,
                                                 const float* __restrict__ Wimg) {
    __shared__ float As[16][128];
    __shared__ float Bs[16][128];
    int tid = threadIdx.x;
    int nBase = blockIdx.x * 128;
    int mBase = blockIdx.y * 128;
    int lr = tid >> 1, lk = (tid & 1) * 8;
    int arow = mBase + lr;
    bool aok = arow < BB;

    u64 acc[8][4];
#pragma unroll
    for (int i = 0; i < 8; i++)
#pragma unroll
        for (int j = 0; j < 4; j++) acc[i][j] = 0ULL;
    int tx = tid & 15, ty = tid >> 4;

    for (int k0 = 0; k0 < 1024; k0 += 16) {
        int kk = k0 + lk;
        float4 a0 = make_float4(0.f, 0.f, 0.f, 0.f), a1 = a0;
        if (aok) {
            const float* p = (kk < 512) ? (init_actv + (size_t)arow * 512 + kk)
                                        : (image0 + (size_t)arow * 512 + (kk - 512));
            a0 = *(const float4*)p; a1 = *(const float4*)(p + 4);
        }
        const float* q = (kk < 512) ? (Wpc + (size_t)(nBase + lr) * 512 + kk)
                                    : (Wimg + (size_t)(nBase + lr) * 512 + (kk - 512));
        float4 b0 = *(const float4*)q;
        float4 b1 = *(const float4*)(q + 4);
        stage_store(As, lk, lr, a0, a1);
        stage_store(Bs, lk, lr, b0, b1);
        __syncthreads();
        mm128(As, Bs, acc, ty, tx);
        __syncthreads();
    }
    int row0 = mBase + ty * 8;
    int col0 = nBase + tx * 8;
#pragma unroll
    for (int i = 0; i < 8; i++) {
        int row = row0 + i;
        if (row >= BB) break;
        __nv_bfloat16* whi = ghi_buf + (size_t)row * NGG + col0;
        __nv_bfloat16* wlo = glo_buf + (size_t)row * NGG + col0;
#pragma unroll
        for (int j = 0; j < 4; j++) {
            float2 c = unpack2(acc[i][j]);
            __nv_bfloat16 hx = __float2bfloat16(c.x);
            __nv_bfloat16 hy = __float2bfloat16(c.y);
            whi[2 * j] = hx; whi[2 * j + 1] = hy;
            wlo[2 * j]     = __float2bfloat16(c.x - __bfloat162float(hx));
            wlo[2 * j + 1] = __float2bfloat16(c.y - __bfloat162float(hy));
        }
    }
}

extern "C" void kernel_launch(void* const* d_in, const int* in_sizes, int n_in,
                              void* d_out, int out_size) {
    const float* image     = (const float*)d_in[0];
    const float* vel       = (const float*)d_in[1];
    const float* init_actv = (const float*)d_in[2];
    const float* W_enc_pc  = (const float*)d_in[3];
    const float* W_enc_img = (const float*)d_in[4];
    const float* W_v2h     = (const float*)d_in[5];
    const float* W_h2h     = (const float*)d_in[6];
    const float* W_dec_pc  = (const float*)d_in[7];
    const float* W_dec_img = (const float*)d_in[8];
    float* out = (float*)d_out;

    static bool init_done = false;
    if (!init_done) {
        cudaFuncSetAttribute(step_mma, cudaFuncAttributeMaxDynamicSharedMemorySize, 2 * STAGE_S);
        cudaFuncSetAttribute(dec_mma, cudaFuncAttributeMaxDynamicSharedMemorySize, 3 * STAGE_D);
        init_done = true;
    }

    // fused weight conversion: W_h2h (16384 blocks) + decoder W (4096 blocks)
    wconv_all<<<dim3(20480), dim3(256)>>>(W_h2h, W_dec_pc, W_dec_img);
    h0_kernel<<<dim3(NGG / 128, (BB + 127) / 128), dim3(256)>>>(init_actv, image, W_enc_pc, W_enc_img);

    for (int t = 0; t < TT; t++) {
        step_mma<<<dim3(NGG / 64, 2), dim3(256), 2 * STAGE_S>>>(t, vel + (size_t)t * BB * 2, W_v2h);
    }

    dec_mma<<<dim3(1024 / 128, (TBROWS + 127) / 128), dim3(256), 3 * STAGE_D>>>(out);
}

// round 17
// speedup vs baseline: 1.5590x; 1.5590x over previous
#include <cuda_runtime.h>
#include <cuda_bf16.h>
#include <cstdint>

#define TT    100
#define BB    200
#define NGG   4096
#define NPP   512
#define TBROWS (TT * BB)   // 20000
#define MPAD  256
#define KC    128
#define NC    (NGG / KC)   // 32
#define KCD   64
#define NCD   (NGG / KCD)  // 64 (decoder)

typedef unsigned long long u64;
#define SLOT ((size_t)MPAD * NGG)

// ---------------- static device scratch (allocation-free) ----------------
__device__ __nv_bfloat16 ghi_buf[(size_t)(TT + 1) * MPAD * NGG];  // 212 MB, pad rows stay 0
__device__ __nv_bfloat16 glo_buf[(size_t)(TT + 1) * MPAD * NGG];  // 212 MB
__device__ __nv_bfloat16 Whi_d[(size_t)NGG * NGG];                // 33.5 MB
__device__ __nv_bfloat16 Wlo_d[(size_t)NGG * NGG];                // 33.5 MB
__device__ __nv_bfloat16 decWhi[(size_t)1024 * NGG];              // 8.4 MB
__device__ __nv_bfloat16 decWlo[(size_t)1024 * NGG];

// ---------------- helpers ----------------
static __device__ __forceinline__ uint32_t smem_u32(const void* p) {
    uint32_t a;
    asm("{ .reg .u64 t; cvta.to.shared.u64 t, %1; cvt.u32.u64 %0, t; }" : "=r"(a) : "l"(p));
    return a;
}
static __device__ __forceinline__ void cpa16(uint32_t d, const void* g) {
    asm volatile("cp.async.cg.shared.global [%0], [%1], 16;" :: "r"(d), "l"(g));
}
static __device__ __forceinline__ void cpa16z(uint32_t d, const void* g, uint32_t n) {
    asm volatile("cp.async.cg.shared.global [%0], [%1], 16, %2;" :: "r"(d), "l"(g), "r"(n));
}
#define CP_COMMIT() asm volatile("cp.async.commit_group;" ::: "memory")
#define CP_WAIT1()  asm volatile("cp.async.wait_group 1;" ::: "memory")
#define SWZ(x) ((x) ^ (((x) >> 3) & 0x70))

static __device__ __forceinline__ void ldsm4(uint32_t* r, uint32_t a) {
    asm volatile("ldmatrix.sync.aligned.m8n8.x4.shared.b16 {%0,%1,%2,%3}, [%4];"
                 : "=r"(r[0]), "=r"(r[1]), "=r"(r[2]), "=r"(r[3]) : "r"(a));
}
static __device__ __forceinline__ void mma_bf16(float* c, const uint32_t* a, const uint32_t* b) {
    asm volatile("mma.sync.aligned.m16n8k16.row.col.f32.bf16.bf16.f32 "
                 "{%0,%1,%2,%3},{%4,%5,%6,%7},{%8,%9},{%0,%1,%2,%3};"
                 : "+f"(c[0]), "+f"(c[1]), "+f"(c[2]), "+f"(c[3])
                 : "r"(a[0]), "r"(a[1]), "r"(a[2]), "r"(a[3]), "r"(b[0]), "r"(b[1]));
}

// ---- 32M x 32N warp tile over one 64-wide k sub-chunk, bf16x3, term-major ----
static __device__ __forceinline__ void mma_chunk32(uint32_t sAhi, uint32_t sAlo,
                                                   uint32_t sBhi, uint32_t sBlo,
                                                   int aRowBase, int bRowBase, int lane,
                                                   float (*acc)[4][4]) {   // acc[2][4][4]
#pragma unroll
    for (int j = 0; j < 4; j++) {
        uint32_t aHi[2][4], aLo[2][4], bHi[4][2], bLo[4][2];
        int kbA = j * 32 + (lane & 16);
#pragma unroll
        for (int mg = 0; mg < 2; mg++) {
            int row = aRowBase + 16 * mg + (lane & 15);
            uint32_t off = SWZ((uint32_t)(row * 128 + kbA));
            ldsm4(aHi[mg], sAhi + off);
            ldsm4(aLo[mg], sAlo + off);
        }
        int kbB = j * 32 + ((lane & 8) << 1);
#pragma unroll
        for (int p = 0; p < 2; p++) {
            int nrow = bRowBase + 16 * p + ((lane & 16) >> 1) + (lane & 7);
            uint32_t off = SWZ((uint32_t)(nrow * 128 + kbB));
            uint32_t r4[4], s4[4];
            ldsm4(r4, sBhi + off);
            ldsm4(s4, sBlo + off);
            bHi[2 * p][0] = r4[0]; bHi[2 * p][1] = r4[1];
            bHi[2 * p + 1][0] = r4[2]; bHi[2 * p + 1][1] = r4[3];
            bLo[2 * p][0] = s4[0]; bLo[2 * p][1] = s4[1];
            bLo[2 * p + 1][0] = s4[2]; bLo[2 * p + 1][1] = s4[3];
        }
#pragma unroll
        for (int mg = 0; mg < 2; mg++)
#pragma unroll
            for (int ng = 0; ng < 4; ng++) mma_bf16(acc[mg][ng], aHi[mg], bHi[ng]);
#pragma unroll
        for (int mg = 0; mg < 2; mg++)
#pragma unroll
            for (int ng = 0; ng < 4; ng++) mma_bf16(acc[mg][ng], aHi[mg], bLo[ng]);
#pragma unroll
        for (int mg = 0; mg < 2; mg++)
#pragma unroll
            for (int ng = 0; ng < 4; ng++) mma_bf16(acc[mg][ng], aLo[mg], bHi[ng]);
    }
}

// ---- 64M x 32N warp tile (decoder) ----
static __device__ __forceinline__ void mma_chunk(uint32_t sAhi, uint32_t sAlo,
                                                 uint32_t sBhi, uint32_t sBlo,
                                                 int aRowBase, int bRowBase, int lane,
                                                 float (*acc)[4][4]) {   // acc[4][4][4]
#pragma unroll
    for (int j = 0; j < 4; j++) {
        uint32_t aHi[4][4], aLo[4][4], bHi[4][2], bLo[4][2];
        int kbA = j * 32 + (lane & 16);
#pragma unroll
        for (int mg = 0; mg < 4; mg++) {
            int row = aRowBase + 16 * mg + (lane & 15);
            uint32_t off = SWZ((uint32_t)(row * 128 + kbA));
            ldsm4(aHi[mg], sAhi + off);
            ldsm4(aLo[mg], sAlo + off);
        }
        int kbB = j * 32 + ((lane & 8) << 1);
#pragma unroll
        for (int p = 0; p < 2; p++) {
            int nrow = bRowBase + 16 * p + ((lane & 16) >> 1) + (lane & 7);
            uint32_t off = SWZ((uint32_t)(nrow * 128 + kbB));
            uint32_t r4[4], s4[4];
            ldsm4(r4, sBhi + off);
            ldsm4(s4, sBlo + off);
            bHi[2 * p][0] = r4[0]; bHi[2 * p][1] = r4[1];
            bHi[2 * p + 1][0] = r4[2]; bHi[2 * p + 1][1] = r4[3];
            bLo[2 * p][0] = s4[0]; bLo[2 * p][1] = s4[1];
            bLo[2 * p + 1][0] = s4[2]; bLo[2 * p + 1][1] = s4[3];
        }
#pragma unroll
        for (int mg = 0; mg < 4; mg++)
#pragma unroll
            for (int ng = 0; ng < 4; ng++) {
                mma_bf16(acc[mg][ng], aHi[mg], bHi[ng]);
                mma_bf16(acc[mg][ng], aHi[mg], bLo[ng]);
                mma_bf16(acc[mg][ng], aLo[mg], bHi[ng]);
            }
    }
}

// ================= step: slot[t+1] = relu(vel_enc + slot[t] @ Wh^T) =========
// Block 128M x 64N, 256 threads (8 warps: 4m x 2n, warp tile 32x32).
// grid (64 n, 2 m) = 128 CTAs, 1/SM. KC=128 as two 64-wide SW128 sub-tiles,
// 2-stage ring (192KB smem). EXACT R11 configuration (best measured: 72us).
#define AHI0 0
#define ALO0 32768
#define BHI0 65536
#define BLO0 81920
#define STAGE_S 98304
__global__ void __launch_bounds__(256) step_mma(int t,
                                                const float* __restrict__ vel_t,
                                                const float* __restrict__ Wv) {
    extern __shared__ __align__(1024) char smem[];
    uint32_t sb = smem_u32(smem);
    const int tid = threadIdx.x, lane = tid & 31, w = tid >> 5;
    const int mw = w >> 1, nw = w & 1;                 // 4m x 2n
    const int nBase = blockIdx.x * 64, mBase = blockIdx.y * 128;
    const __nv_bfloat16* pAhi = ghi_buf + (size_t)t * SLOT;
    const __nv_bfloat16* pAlo = glo_buf + (size_t)t * SLOT;

    // A: 128 rows x 16 (16B units); 8 sweeps of 256 threads each for hi (and lo)
    size_t aSrc[8]; uint32_t aDst[8];
#pragma unroll
    for (int i = 0; i < 8; i++) {
        int u = i * 256 + tid, row = u >> 4, k16 = u & 15;
        int sub = k16 >> 3, k8 = k16 & 7;
        aSrc[i] = (size_t)(mBase + row) * NGG + k16 * 8;
        aDst[i] = sub * 16384 + SWZ((uint32_t)(row * 128 + k8 * 16));
    }
    // B: 64 rows x 16; 4 sweeps
    size_t bSrc[4]; uint32_t bDst[4];
#pragma unroll
    for (int i = 0; i < 4; i++) {
        int u = i * 256 + tid, row = u >> 4, k16 = u & 15;
        int sub = k16 >> 3, k8 = k16 & 7;
        bSrc[i] = (size_t)(nBase + row) * NGG + k16 * 8;
        bDst[i] = sub * 8192 + SWZ((uint32_t)(row * 128 + k8 * 16));
    }

    auto loadc = [&](int c, int s) {
        uint32_t base = sb + s * STAGE_S;
        int ko = c * KC;
#pragma unroll
        for (int i = 0; i < 8; i++) {
            cpa16(base + AHI0 + aDst[i], pAhi + aSrc[i] + ko);
            cpa16(base + ALO0 + aDst[i], pAlo + aSrc[i] + ko);
        }
#pragma unroll
        for (int i = 0; i < 4; i++) {
            cpa16(base + BHI0 + bDst[i], Whi_d + bSrc[i] + ko);
            cpa16(base + BLO0 + bDst[i], Wlo_d + bSrc[i] + ko);
        }
        CP_COMMIT();
    };

    float acc[2][4][4];
#pragma unroll
    for (int a = 0; a < 2; a++)
#pragma unroll
        for (int b = 0; b < 4; b++)
#pragma unroll
            for (int e = 0; e < 4; e++) acc[a][b][e] = 0.f;

    loadc(0, 0); loadc(1, 1);
    for (int c = 0; c < NC; c++) {
        CP_WAIT1();
        __syncthreads();
        uint32_t base = sb + (c & 1) * STAGE_S;
        mma_chunk32(base + AHI0, base + ALO0, base + BHI0, base + BLO0,
                    32 * mw, 32 * nw, lane, acc);
        mma_chunk32(base + AHI0 + 16384, base + ALO0 + 16384,
                    base + BHI0 + 8192, base + BLO0 + 8192,
                    32 * mw, 32 * nw, lane, acc);
        __syncthreads();
        if (c + 2 < NC) loadc(c + 2, c & 1); else CP_COMMIT();
    }

    __nv_bfloat16* oHi = ghi_buf + (size_t)(t + 1) * SLOT;
    __nv_bfloat16* oLo = glo_buf + (size_t)(t + 1) * SLOT;
#pragma unroll
    for (int mg = 0; mg < 2; mg++) {
        int r0 = 32 * mw + 16 * mg + (lane >> 2);
        int m0 = mBase + r0, m1 = m0 + 8;
        float v00 = 0.f, v01 = 0.f, v10 = 0.f, v11 = 0.f;
        if (m0 < BB) { v00 = vel_t[m0 * 2]; v01 = vel_t[m0 * 2 + 1]; }
        if (m1 < BB) { v10 = vel_t[m1 * 2]; v11 = vel_t[m1 * 2 + 1]; }
#pragma unroll
        for (int ng = 0; ng < 4; ng++) {
            int c0 = nBase + 32 * nw + 8 * ng + (lane & 3) * 2;
            float4 wv = *(const float4*)&Wv[c0 * 2];
            float* d = acc[mg][ng];
            if (m0 < BB) {
                float x0 = fmaxf(d[0] + v00 * wv.x + v01 * wv.y, 0.f);
                float x1 = fmaxf(d[1] + v00 * wv.z + v01 * wv.w, 0.f);
                __nv_bfloat16 h0 = __float2bfloat16(x0), h1 = __float2bfloat16(x1);
                __nv_bfloat162 hh; hh.x = h0; hh.y = h1;
                __nv_bfloat162 ll;
                ll.x = __float2bfloat16(x0 - __bfloat162float(h0));
                ll.y = __float2bfloat16(x1 - __bfloat162float(h1));
                *(__nv_bfloat162*)&oHi[(size_t)m0 * NGG + c0] = hh;
                *(__nv_bfloat162*)&oLo[(size_t)m0 * NGG + c0] = ll;
            }
            if (m1 < BB) {
                float x0 = fmaxf(d[2] + v10 * wv.x + v11 * wv.y, 0.f);
                float x1 = fmaxf(d[3] + v10 * wv.z + v11 * wv.w, 0.f);
                __nv_bfloat16 h0 = __float2bfloat16(x0), h1 = __float2bfloat16(x1);
                __nv_bfloat162 hh; hh.x = h0; hh.y = h1;
                __nv_bfloat162 ll;
                ll.x = __float2bfloat16(x0 - __bfloat162float(h0));
                ll.y = __float2bfloat16(x1 - __bfloat162float(h1));
                *(__nv_bfloat162*)&oHi[(size_t)m1 * NGG + c0] = hh;
                *(__nv_bfloat162*)&oLo[(size_t)m1 * NGG + c0] = ll;
            }
        }
    }
}

// ================= decoder: place | sigmoid(image) via bf16x3 mma ===========
// grid (8 n, 157 m), 256 threads (8 warps: 2m x 4n), 3-stage pipeline (R11).
#define STAGE_D 65536   // Ahi 16K | Alo 16K | Bhi 16K | Blo 16K
__global__ void __launch_bounds__(256) dec_mma(float* __restrict__ out) {
    extern __shared__ __align__(1024) char smem[];
    uint32_t sb = smem_u32(smem);
    const int tid = threadIdx.x, lane = tid & 31, w = tid >> 5;
    const int mh = w >> 2, wn = w & 3;
    const int nBase = blockIdx.x * 128, mBase = blockIdx.y * 128;

    size_t aSrc[4]; uint32_t aDst[4], aVal[4];
#pragma unroll
    for (int i = 0; i < 4; i++) {
        int u = i * 256 + tid, row = u >> 3, k8 = u & 7;
        int arow = mBase + row;
        bool ok = arow < TBROWS;
        int tt = ok ? (arow / 200) : 0;
        int b = ok ? (arow - tt * 200) : 0;
        aSrc[i] = ((size_t)(tt + 1) * MPAD + b) * NGG + k8 * 8;
        aDst[i] = SWZ((uint32_t)(row * 128 + k8 * 16));
        aVal[i] = ok ? 16u : 0u;
    }
    size_t bSrc[4]; uint32_t bDst[4];
#pragma unroll
    for (int i = 0; i < 4; i++) {
        int u = i * 256 + tid, row = u >> 3, k8 = u & 7;
        bSrc[i] = (size_t)(nBase + row) * NGG + k8 * 8;
        bDst[i] = SWZ((uint32_t)(row * 128 + k8 * 16));
    }

    auto loadc = [&](int c, int s) {
        uint32_t base = sb + s * STAGE_D;
        int ko = c * KCD;
#pragma unroll
        for (int i = 0; i < 4; i++) {
            cpa16z(base + aDst[i], ghi_buf + aSrc[i] + ko, aVal[i]);
            cpa16z(base + 16384 + aDst[i], glo_buf + aSrc[i] + ko, aVal[i]);
        }
#pragma unroll
        for (int i = 0; i < 4; i++) {
            cpa16(base + 32768 + bDst[i], decWhi + bSrc[i] + ko);
            cpa16(base + 49152 + bDst[i], decWlo + bSrc[i] + ko);
        }
        CP_COMMIT();
    };

    float acc[4][4][4];
#pragma unroll
    for (int a = 0; a < 4; a++)
#pragma unroll
        for (int b = 0; b < 4; b++)
#pragma unroll
            for (int e = 0; e < 4; e++) acc[a][b][e] = 0.f;

    loadc(0, 0); loadc(1, 1);
    for (int c = 0; c < NCD; c++) {
        CP_WAIT1();
        __syncthreads();
        if (c + 2 < NCD) loadc(c + 2, (c + 2) % 3); else CP_COMMIT();
        uint32_t base = sb + (c % 3) * STAGE_D;
        mma_chunk(base, base + 16384, base + 32768, base + 49152,
                  64 * mh, 32 * wn, lane, acc);
    }

    const size_t IMG_OFF = (size_t)TBROWS * NPP;
#pragma unroll
    for (int mg = 0; mg < 4; mg++) {
        int r0 = 64 * mh + 16 * mg + (lane >> 2);
        int m0 = mBase + r0, m1 = m0 + 8;
#pragma unroll
        for (int ng = 0; ng < 4; ng++) {
            int c0 = nBase + 32 * wn + 8 * ng + (lane & 3) * 2;
            float* d = acc[mg][ng];
            if (c0 < NPP) {
                if (m0 < TBROWS) *(float2*)&out[(size_t)m0 * NPP + c0] = make_float2(d[0], d[1]);
                if (m1 < TBROWS) *(float2*)&out[(size_t)m1 * NPP + c0] = make_float2(d[2], d[3]);
            } else {
                int ci = c0 - NPP;
                if (m0 < TBROWS) {
                    float2 s = make_float2(1.f / (1.f + __expf(-d[0])), 1.f / (1.f + __expf(-d[1])));
                    *(float2*)&out[IMG_OFF + (size_t)m0 * NPP + ci] = s;
                }
                if (m1 < TBROWS) {
                    float2 s = make_float2(1.f / (1.f + __expf(-d[2])), 1.f / (1.f + __expf(-d[3])));
                    *(float2*)&out[IMG_OFF + (size_t)m1 * NPP + ci] = s;
                }
            }
        }
    }
}

// ================= fused weight conversion (W_h2h + decoder W) =============
__global__ void __launch_bounds__(256) wconv_all(const float* __restrict__ W,
                                                 const float* __restrict__ Wpc,
                                                 const float* __restrict__ Wimg) {
    if (blockIdx.x < 16384) {
        size_t i = ((size_t)blockIdx.x * 256 + threadIdx.x) * 4;
        float4 w = *(const float4*)&W[i];
        __nv_bfloat16 h0 = __float2bfloat16(w.x), h1 = __float2bfloat16(w.y);
        __nv_bfloat16 h2 = __float2bfloat16(w.z), h3 = __float2bfloat16(w.w);
        Whi_d[i] = h0; Whi_d[i + 1] = h1; Whi_d[i + 2] = h2; Whi_d[i + 3] = h3;
        Wlo_d[i]     = __float2bfloat16(w.x - __bfloat162float(h0));
        Wlo_d[i + 1] = __float2bfloat16(w.y - __bfloat162float(h1));
        Wlo_d[i + 2] = __float2bfloat16(w.z - __bfloat162float(h2));
        Wlo_d[i + 3] = __float2bfloat16(w.w - __bfloat162float(h3));
    } else {
        size_t i = (((size_t)(blockIdx.x - 16384)) * 256 + threadIdx.x) * 4;
        int n = (int)(i >> 12);
        int kk = (int)(i & 4095);
        const float* src = (n < NPP) ? (Wpc + (size_t)n * NGG + kk)
                                     : (Wimg + (size_t)(n - NPP) * NGG + kk);
        float4 w = *(const float4*)src;
        __nv_bfloat16 h0 = __float2bfloat16(w.x), h1 = __float2bfloat16(w.y);
        __nv_bfloat16 h2 = __float2bfloat16(w.z), h3 = __float2bfloat16(w.w);
        decWhi[i] = h0; decWhi[i + 1] = h1; decWhi[i + 2] = h2; decWhi[i + 3] = h3;
        decWlo[i]     = __float2bfloat16(w.x - __bfloat162float(h0));
        decWlo[i + 1] = __float2bfloat16(w.y - __bfloat162float(h1));
        decWlo[i + 2] = __float2bfloat16(w.z - __bfloat162float(h2));
        decWlo[i + 3] = __float2bfloat16(w.w - __bfloat162float(h3));
    }
}

// ================= h0 (SIMT fp32, K=1024 concat) -> slot 0 hi/lo ============
static __device__ __forceinline__ u64 pack_dup(float x) {
    u64 r; asm("mov.b64 %0, {%1, %1};" : "=l"(r) : "f"(x)); return r;
}
static __device__ __forceinline__ void fma2(u64 &d, u64 a, u64 b) {
    asm("fma.rn.f32x2 %0, %1, %2, %0;" : "+l"(d) : "l"(a), "l"(b));
}
static __device__ __forceinline__ float2 unpack2(u64 v) {
    float2 f; asm("mov.b64 {%0, %1}, %2;" : "=f"(f.x), "=f"(f.y) : "l"(v)); return f;
}
static __device__ __forceinline__ void mm128(const float (*As)[128], const float (*Bs)[128],
                                             u64 acc[8][4], int ty, int tx) {
#pragma unroll
    for (int k = 0; k < 16; k++) {
        float4 av0 = *(const float4*)&As[k][ty * 8];
        float4 av1 = *(const float4*)&As[k][ty * 8 + 4];
        const u64* bp = (const u64*)&Bs[k][tx * 8];
        u64 b0 = bp[0], b1 = bp[1], b2 = bp[2], b3 = bp[3];
        u64 ad[8];
        ad[0] = pack_dup(av0.x); ad[1] = pack_dup(av0.y);
        ad[2] = pack_dup(av0.z); ad[3] = pack_dup(av0.w);
        ad[4] = pack_dup(av1.x); ad[5] = pack_dup(av1.y);
        ad[6] = pack_dup(av1.z); ad[7] = pack_dup(av1.w);
#pragma unroll
        for (int i = 0; i < 8; i++) {
            fma2(acc[i][0], ad[i], b0); fma2(acc[i][1], ad[i], b1);
            fma2(acc[i][2], ad[i], b2); fma2(acc[i][3], ad[i], b3);
        }
    }
}
static __device__ __forceinline__ void stage_store(float (*dst)[128], int lk, int lr,
                                                   float4 v0, float4 v1) {
    dst[lk + 0][lr] = v0.x; dst[lk + 1][lr] = v0.y; dst[lk + 2][lr] = v0.z; dst[lk + 3][lr] = v0.w;
    dst[lk + 4][lr] = v1.x; dst[lk + 5][lr] = v1.y; dst[lk + 6][lr] = v1.z; dst[lk + 7][lr] = v1.w;
}

__global__ void __launch_bounds__(256) h0_kernel(const float* __restrict__ init_actv,
                                                 const float* __restrict__ image0,
                                                 const float* __restrict__ Wpc,
                                                 const float* __restrict__ Wimg) {
    __shared__ float As[16][128];
    __shared__ float Bs[16][128];
    int tid = threadIdx.x;
    int nBase = blockIdx.x * 128;
    int mBase = blockIdx.y * 128;
    int lr = tid >> 1, lk = (tid & 1) * 8;
    int arow = mBase + lr;
    bool aok = arow < BB;

    u64 acc[8][4];
#pragma unroll
    for (int i = 0; i < 8; i++)
#pragma unroll
        for (int j = 0; j < 4; j++) acc[i][j] = 0ULL;
    int tx = tid & 15, ty = tid >> 4;

    for (int k0 = 0; k0 < 1024; k0 += 16) {
        int kk = k0 + lk;
        float4 a0 = make_float4(0.f, 0.f, 0.f, 0.f), a1 = a0;
        if (aok) {
            const float* p = (kk < 512) ? (init_actv + (size_t)arow * 512 + kk)
                                        : (image0 + (size_t)arow * 512 + (kk - 512));
            a0 = *(const float4*)p; a1 = *(const float4*)(p + 4);
        }
        const float* q = (kk < 512) ? (Wpc + (size_t)(nBase + lr) * 512 + kk)
                                    : (Wimg + (size_t)(nBase + lr) * 512 + (kk - 512));
        float4 b0 = *(const float4*)q;
        float4 b1 = *(const float4*)(q + 4);
        stage_store(As, lk, lr, a0, a1);
        stage_store(Bs, lk, lr, b0, b1);
        __syncthreads();
        mm128(As, Bs, acc, ty, tx);
        __syncthreads();
    }
    int row0 = mBase + ty * 8;
    int col0 = nBase + tx * 8;
#pragma unroll
    for (int i = 0; i < 8; i++) {
        int row = row0 + i;
        if (row >= BB) break;
        __nv_bfloat16* whi = ghi_buf + (size_t)row * NGG + col0;
        __nv_bfloat16* wlo = glo_buf + (size_t)row * NGG + col0;
#pragma unroll
        for (int j = 0; j < 4; j++) {
            float2 c = unpack2(acc[i][j]);
            __nv_bfloat16 hx = __float2bfloat16(c.x);
            __nv_bfloat16 hy = __float2bfloat16(c.y);
            whi[2 * j] = hx; whi[2 * j + 1] = hy;
            wlo[2 * j]     = __float2bfloat16(c.x - __bfloat162float(hx));
            wlo[2 * j + 1] = __float2bfloat16(c.y - __bfloat162float(hy));
        }
    }
}

extern "C" void kernel_launch(void* const* d_in, const int* in_sizes, int n_in,
                              void* d_out, int out_size) {
    const float* image     = (const float*)d_in[0];
    const float* vel       = (const float*)d_in[1];
    const float* init_actv = (const float*)d_in[2];
    const float* W_enc_pc  = (const float*)d_in[3];
    const float* W_enc_img = (const float*)d_in[4];
    const float* W_v2h     = (const float*)d_in[5];
    const float* W_h2h     = (const float*)d_in[6];
    const float* W_dec_pc  = (const float*)d_in[7];
    const float* W_dec_img = (const float*)d_in[8];
    float* out = (float*)d_out;

    static bool init_done = false;
    if (!init_done) {
        cudaFuncSetAttribute(step_mma, cudaFuncAttributeMaxDynamicSharedMemorySize, 2 * STAGE_S);
        cudaFuncSetAttribute(dec_mma, cudaFuncAttributeMaxDynamicSharedMemorySize, 3 * STAGE_D);
        init_done = true;
    }

    // fused weight conversion: W_h2h (16384 blocks) + decoder W (4096 blocks)
    wconv_all<<<dim3(20480), dim3(256)>>>(W_h2h, W_dec_pc, W_dec_img);
    h0_kernel<<<dim3(NGG / 128, (BB + 127) / 128), dim3(256)>>>(init_actv, image, W_enc_pc, W_enc_img);

    for (int t = 0; t < TT; t++) {
        step_mma<<<dim3(NGG / 64, 2), dim3(256), 2 * STAGE_S>>>(t, vel + (size_t)t * BB * 2, W_v2h);
    }

    dec_mma<<<dim3(1024 / 128, (TBROWS + 127) / 128), dim3(256), 3 * STAGE_D>>>(out);
}